// round 15
// baseline (speedup 1.0000x reference)
#include <cuda_runtime.h>
#include <cuda_bf16.h>
#include <math.h>
#include <cstdint>

#define B_    4
#define S_    2048
#define DIM_  1024
#define H_    16
#define HD_   64
#define BSD   (B_ * S_ * DIM_)     // 8,388,608
#define MROWS (B_ * S_)            // 8192
#define NK    (DIM_ * DIM_)        // 1,048,576

// ---------------- device scratch (no cudaMalloc allowed) -------------------
__device__ __nv_bfloat16 g_xhi[BSD], g_xlo[BSD];
__device__ __nv_bfloat16 g_chi[BSD], g_clo[BSD];
__device__ __nv_bfloat16 g_whi[4 * NK], g_wlo[4 * NK];
__device__ __nv_bfloat16 g_qhi[BSD], g_qlo[BSD];
__device__ __nv_bfloat16 g_khi[BSD], g_klo[BSD];
__device__ __nv_bfloat16 g_vThi[BSD], g_vTlo[BSD];   // layout (b,h,d,s)
__device__ float2 g_rtab[S_ * 32];

// ---------------- PTX helpers (sm_80+ only; NO a-suffix features) ----------
__device__ __forceinline__ uint32_t smem_u32(const void* p) {
    uint32_t a;
    asm("{ .reg .u64 t; cvta.to.shared.u64 t, %1; cvt.u32.u64 %0, t; }"
        : "=r"(a) : "l"(p));
    return a;
}
__device__ __forceinline__ void cp16(uint32_t dst, const void* src) {
    asm volatile("cp.async.cg.shared.global [%0], [%1], 16;"
                 :: "r"(dst), "l"(src));
}
#define CP_COMMIT() asm volatile("cp.async.commit_group;" ::: "memory")
#define CP_WAIT(n)  asm volatile("cp.async.wait_group %0;" :: "n"(n) : "memory")

__device__ __forceinline__ void ldsm_x4(uint32_t* r, uint32_t addr) {
    asm volatile("ldmatrix.sync.aligned.m8n8.x4.shared.b16 {%0,%1,%2,%3}, [%4];"
                 : "=r"(r[0]), "=r"(r[1]), "=r"(r[2]), "=r"(r[3]) : "r"(addr));
}
__device__ __forceinline__ void mma16816(float* c, const uint32_t* a, const uint32_t* b) {
    asm volatile(
        "mma.sync.aligned.m16n8k16.row.col.f32.bf16.bf16.f32 "
        "{%0,%1,%2,%3}, {%4,%5,%6,%7}, {%8,%9}, {%0,%1,%2,%3};"
        : "+f"(c[0]), "+f"(c[1]), "+f"(c[2]), "+f"(c[3])
        : "r"(a[0]), "r"(a[1]), "r"(a[2]), "r"(a[3]), "r"(b[0]), "r"(b[1]));
}

__device__ __forceinline__ void pack_hl(uint32_t& ph, uint32_t& pl, float a, float b) {
    __nv_bfloat162 hb = __floats2bfloat162_rn(a, b);
    float2 hf = __bfloat1622float2(hb);
    __nv_bfloat162 lb = __floats2bfloat162_rn(a - hf.x, b - hf.y);
    ph = reinterpret_cast<uint32_t&>(hb);
    pl = reinterpret_cast<uint32_t&>(lb);
}

// ---------------------------------------------------------------------------
// fused split: x + 4 weight matrices, fp32 -> (hi, lo) bf16, one launch.
// ---------------------------------------------------------------------------
#define X_N4 (BSD / 4)    // 2,097,152
#define W_N4 (NK / 4)     // 262,144
#define TOT_N4 (X_N4 + 4 * W_N4)

__global__ __launch_bounds__(256) void split_all(
    const float* __restrict__ x,
    const float* __restrict__ W0, const float* __restrict__ W1,
    const float* __restrict__ W2, const float* __restrict__ W3,
    __nv_bfloat16* __restrict__ xhi, __nv_bfloat16* __restrict__ xlo,
    __nv_bfloat16* __restrict__ whi, __nv_bfloat16* __restrict__ wlo)
{
    const int i = blockIdx.x * blockDim.x + threadIdx.x;
    if (i >= TOT_N4) return;

    const float* src;
    __nv_bfloat16 *hi, *lo;
    int j;
    if (i < X_N4) {
        src = x; hi = xhi; lo = xlo; j = i;
    } else {
        const int wi = i - X_N4;
        const int w = wi >> 18;            // /262144
        j = wi & (W_N4 - 1);
        src = (w == 0) ? W0 : (w == 1) ? W1 : (w == 2) ? W2 : W3;
        hi = whi + (size_t)w * NK;
        lo = wlo + (size_t)w * NK;
    }

    float4 v = ((const float4*)src)[j];
    __nv_bfloat16 h0 = __float2bfloat16(v.x);
    __nv_bfloat16 h1 = __float2bfloat16(v.y);
    __nv_bfloat16 h2 = __float2bfloat16(v.z);
    __nv_bfloat16 h3 = __float2bfloat16(v.w);
    __nv_bfloat16 l0 = __float2bfloat16(v.x - __bfloat162float(h0));
    __nv_bfloat16 l1 = __float2bfloat16(v.y - __bfloat162float(h1));
    __nv_bfloat16 l2 = __float2bfloat16(v.z - __bfloat162float(h2));
    __nv_bfloat16 l3 = __float2bfloat16(v.w - __bfloat162float(h3));
    __nv_bfloat162* hp = (__nv_bfloat162*)(hi + (size_t)j * 4);
    __nv_bfloat162* lp = (__nv_bfloat162*)(lo + (size_t)j * 4);
    hp[0] = __nv_bfloat162(h0, h1); hp[1] = __nv_bfloat162(h2, h3);
    lp[0] = __nv_bfloat162(l0, l1); lp[1] = __nv_bfloat162(l2, l3);
}

// ---------------------------------------------------------------------------
// RoPE angle table (fp64 accuracy): tab[s][i] = (cos, sin) for dim pair (i,i+32)
// ---------------------------------------------------------------------------
__global__ __launch_bounds__(256) void rope_tab(float2* tab)
{
    const int idx = blockIdx.x * 256 + threadIdx.x;   // 0..65535
    const int s = idx >> 5;
    const int i = idx & 31;
    const double inv = exp(-((double)(2 * i) / 64.0) * 9.210340371976184);
    double ang = (double)s * inv;
    const double tp = 6.283185307179586476925287;
    ang -= floor(ang / tp) * tp;
    tab[s * 32 + i] = make_float2((float)cos(ang), (float)sin(ang));
}

// ---------------------------------------------------------------------------
// mma.sync bf16x3-compensated GEMM. CTA 128(M)x256(N), BK=32, 8 warps (2x4),
// warp tile 64x64. 3-stage cp.async, register-rotated bases, ONE barrier/iter.
// INVARIANT (R7, R13): prefetch is issued AFTER compute, never before.
// fused=1 (QKV): RoPE/split/transpose epilogues. fused=0 (O): plain fp32.
// q is pre-scaled by 0.125*log2(e) so flash softmax can use exp2 directly.
// ---------------------------------------------------------------------------
#define BK     32
#define NITER  (DIM_ / BK)          // 32
#define ATILE  16384                // A: 128 rows * 128B (32 bf16 hi|lo)
#define BTILE  32768                // B: 256 rows * 128B
#define STAGEB (ATILE + BTILE)      // 49152
#define FT_PITCH 258
#define GSMEM  (3 * STAGEB)         // 147456 (FT epilogue needs 132096, fits)
#define QSCALE 0.18033688011112042f // 0.125 * log2(e)

__global__ __launch_bounds__(256, 1) void gemm_bf16x3(
    const __nv_bfloat16* __restrict__ Ahi, const __nv_bfloat16* __restrict__ Alo,
    const __nv_bfloat16* __restrict__ Whi, const __nv_bfloat16* __restrict__ Wlo,
    float* __restrict__ C0,
    int fused,
    const float2* __restrict__ rtab,
    __nv_bfloat16* __restrict__ qhi, __nv_bfloat16* __restrict__ qlo,
    __nv_bfloat16* __restrict__ khi, __nv_bfloat16* __restrict__ klo,
    __nv_bfloat16* __restrict__ vThi, __nv_bfloat16* __restrict__ vTlo)
{
    extern __shared__ char smem[];
    const int tid  = threadIdx.x;
    const int wid  = tid >> 5;
    const int lane = tid & 31;
    const int qq   = lane >> 3;
    const int rr   = lane & 7;
    const int wm   = wid >> 2;      // 0..1 (64 M-rows each)
    const int wn   = wid & 3;       // 0..3 (64 N-cols each)
    const int z    = blockIdx.z;

    const __nv_bfloat16* Wh = Whi + (size_t)z * NK;
    const __nv_bfloat16* Wl = Wlo + (size_t)z * NK;

    const int m0 = blockIdx.y * 128;
    const int n0 = blockIdx.x * 256;
    const uint32_t sb = smem_u32(smem);

    float acc[4][8][4];
#pragma unroll
    for (int a = 0; a < 4; a++)
#pragma unroll
        for (int b = 0; b < 8; b++)
#pragma unroll
            for (int c = 0; c < 4; c++) acc[a][b][c] = 0.f;

    auto load_stage = [&](uint32_t dbase, int kc) {
        // A: 128 rows x 8 chunks = 1024
#pragma unroll
        for (int t = 0; t < 4; t++) {
            const int idx = tid + t * 256;
            const int r = idx >> 3, c = idx & 7;    // c: 0-3 hi, 4-7 lo
            const uint32_t doff = r * 128 + ((c ^ (r & 7)) << 4);
            const size_t goff = (size_t)r * DIM_ + kc + (c & 3) * 8;
            cp16(dbase + doff, (c < 4 ? Ahi : Alo) + (size_t)m0 * DIM_ + goff);
        }
        // B: 256 rows x 8 chunks = 2048
#pragma unroll
        for (int t = 0; t < 8; t++) {
            const int idx = tid + t * 256;
            const int r = idx >> 3, c = idx & 7;
            const uint32_t doff = r * 128 + ((c ^ (r & 7)) << 4);
            const size_t goff = (size_t)r * DIM_ + kc + (c & 3) * 8;
            cp16(dbase + ATILE + doff, (c < 4 ? Wh : Wl) + (size_t)n0 * DIM_ + goff);
        }
        CP_COMMIT();
    };

    uint32_t buf0 = sb;                 // current compute stage
    uint32_t buf1 = sb + STAGEB;        // next stage (in flight)
    uint32_t buf2 = sb + 2 * STAGEB;    // fill target (held stage it-1)

    load_stage(buf0, 0);
    load_stage(buf1, BK);

    for (int it = 0; it < NITER; it++) {
        if (it + 1 < NITER) CP_WAIT(1);
        else                CP_WAIT(0);
        __syncthreads();

        const uint32_t abase = buf0;
        const uint32_t bbase = buf0 + ATILE;

#pragma unroll
        for (int ks = 0; ks < 2; ks++) {
            uint32_t bh[8][2], bl[8][2];
            const int bch = 2 * ks + (qq & 1);
#pragma unroll
            for (int np = 0; np < 4; np++) {
                const int brow = wn * 64 + np * 16 + (qq >> 1) * 8 + rr;
                const uint32_t sw = brow * 128;
                uint32_t t[4];
                ldsm_x4(t, bbase + sw + ((bch ^ (brow & 7)) << 4));
                bh[2 * np][0] = t[0]; bh[2 * np][1] = t[1];
                bh[2 * np + 1][0] = t[2]; bh[2 * np + 1][1] = t[3];
                ldsm_x4(t, bbase + sw + (((bch + 4) ^ (brow & 7)) << 4));
                bl[2 * np][0] = t[0]; bl[2 * np][1] = t[1];
                bl[2 * np + 1][0] = t[2]; bl[2 * np + 1][1] = t[3];
            }
            const int ach = 2 * ks + (qq >> 1);
#pragma unroll
            for (int mt = 0; mt < 4; mt++) {
                const int arow = wm * 64 + mt * 16 + (qq & 1) * 8 + rr;
                const uint32_t sw = arow * 128;
                uint32_t ah[4], al[4];
                ldsm_x4(ah, abase + sw + ((ach ^ (arow & 7)) << 4));
                ldsm_x4(al, abase + sw + (((ach + 4) ^ (arow & 7)) << 4));
#pragma unroll
                for (int nt = 0; nt < 8; nt++) mma16816(acc[mt][nt], ah, bh[nt]);
#pragma unroll
                for (int nt = 0; nt < 8; nt++) mma16816(acc[mt][nt], ah, bl[nt]);
#pragma unroll
                for (int nt = 0; nt < 8; nt++) mma16816(acc[mt][nt], al, bh[nt]);
            }
        }

        // prefetch stage it+2 AFTER compute (invariant)
        if (it + 2 < NITER)
            load_stage(buf2, (it + 2) * BK);

        const uint32_t tmp = buf0; buf0 = buf1; buf1 = buf2; buf2 = tmp;
    }

    if (!fused) {
#pragma unroll
        for (int mt = 0; mt < 4; mt++)
#pragma unroll
            for (int nt = 0; nt < 8; nt++) {
                const int row = m0 + wm * 64 + mt * 16 + (lane >> 2);
                const int col = n0 + wn * 64 + nt * 8 + (lane & 3) * 2;
                *(float2*)&C0[(size_t)row * DIM_ + col] =
                    make_float2(acc[mt][nt][0], acc[mt][nt][1]);
                *(float2*)&C0[(size_t)(row + 8) * DIM_ + col] =
                    make_float2(acc[mt][nt][2], acc[mt][nt][3]);
            }
        return;
    }

    // ---- fused epilogue: stage fp32 tile (128 x 256) in smem ----
    __syncthreads();
    float* ft = (float*)smem;
#define FT(r, c) ft[(r) * FT_PITCH + (c)]
#pragma unroll
    for (int mt = 0; mt < 4; mt++)
#pragma unroll
        for (int nt = 0; nt < 8; nt++) {
            const int r = wm * 64 + mt * 16 + (lane >> 2);
            const int c = wn * 64 + nt * 8 + (lane & 3) * 2;
            FT(r, c)     = acc[mt][nt][0];
            FT(r, c + 1) = acc[mt][nt][1];
            FT(r + 8, c)     = acc[mt][nt][2];
            FT(r + 8, c + 1) = acc[mt][nt][3];
        }
    __syncthreads();

    if (z < 2) {
        // RoPE + hi/lo split; tile covers 4 heads (256 cols).
        const int r  = tid >> 1;        // 0..127
        const int g  = tid & 1;
        const int m  = m0 + r;
        const int ss = m & (S_ - 1);
        const float scale = (z == 0) ? QSCALE : 1.0f;
        __nv_bfloat16* dh = (z == 0) ? qhi : khi;
        __nv_bfloat16* dl = (z == 0) ? qlo : klo;
        const float2* trow = rtab + ss * 32;
#pragma unroll
        for (int hh2 = 0; hh2 < 2; hh2++) {
            const int head = g + 2 * hh2;           // 0..3
            const int cb = head * 64;
            const size_t dst = (size_t)m * DIM_ + n0 + cb;
#pragma unroll
            for (int dc = 0; dc < 32; dc += 8) {
                uint32_t h1[4], l1[4], h2[4], l2[4];
#pragma unroll
                for (int j = 0; j < 4; j++) {
                    const int d0 = dc + 2 * j;
                    const float2 cs0 = trow[d0];
                    const float2 cs1 = trow[d0 + 1];
                    const float x1 = FT(r, cb + d0);
                    const float x2 = FT(r, cb + d0 + 32);
                    const float y1 = FT(r, cb + d0 + 1);
                    const float y2 = FT(r, cb + d0 + 33);
                    const float o1 = (x1 * cs0.x - x2 * cs0.y) * scale;
                    const float o2 = (x2 * cs0.x + x1 * cs0.y) * scale;
                    const float p1 = (y1 * cs1.x - y2 * cs1.y) * scale;
                    const float p2 = (y2 * cs1.x + y1 * cs1.y) * scale;
                    pack_hl(h1[j], l1[j], o1, p1);
                    pack_hl(h2[j], l2[j], o2, p2);
                }
                *(uint4*)(dh + dst + dc)      = make_uint4(h1[0], h1[1], h1[2], h1[3]);
                *(uint4*)(dh + dst + dc + 32) = make_uint4(h2[0], h2[1], h2[2], h2[3]);
                *(uint4*)(dl + dst + dc)      = make_uint4(l1[0], l1[1], l1[2], l1[3]);
                *(uint4*)(dl + dst + dc + 32) = make_uint4(l2[0], l2[1], l2[2], l2[3]);
            }
        }
    } else {
        // V transpose + hi/lo split -> (b,h,d,s); 256 cols via 2 passes.
        const int sh = tid & 1;
        const int bb = m0 >> 11, s0loc = (m0 & (S_ - 1)) + sh * 64;
#pragma unroll
        for (int cc = 0; cc < 2; cc++) {
            const int col = cc * 128 + (tid >> 1);
            const int gcol = n0 + col;
            const int h = gcol >> 6, d = gcol & 63;
            const size_t dst = (((size_t)(bb * H_ + h)) * HD_ + d) * S_ + s0loc;
#pragma unroll
            for (int sc = 0; sc < 64; sc += 8) {
                uint32_t hh[4], ll[4];
#pragma unroll
                for (int j = 0; j < 4; j++) {
                    const int srow = sh * 64 + sc + 2 * j;
                    pack_hl(hh[j], ll[j], FT(srow, col), FT(srow + 1, col));
                }
                *(uint4*)(vThi + dst + sc) = make_uint4(hh[0], hh[1], hh[2], hh[3]);
                *(uint4*)(vTlo + dst + sc) = make_uint4(ll[0], ll[1], ll[2], ll[3]);
            }
        }
    }
#undef FT
}

// ---------------------------------------------------------------------------
// Flash attention on mma.sync bf16x3 (frozen at R14 state).
// ---------------------------------------------------------------------------
#define FROW   144                      // 64 bf16 = 128B + 16B pad
#define QTB    (128 * FROW)             // 18432
#define KTB    (64 * FROW)              // 9216
#define FSTAGE (4 * KTB)                // 36864: khi,klo,vhi,vlo
#define FSMEM  (2 * QTB + 2 * FSTAGE)   // 110592

__global__ __launch_bounds__(256, 2) void flash_mma(
    const __nv_bfloat16* __restrict__ qhi, const __nv_bfloat16* __restrict__ qlo,
    const __nv_bfloat16* __restrict__ khi, const __nv_bfloat16* __restrict__ klo,
    const __nv_bfloat16* __restrict__ vhiT, const __nv_bfloat16* __restrict__ vloT,
    __nv_bfloat16* __restrict__ chi, __nv_bfloat16* __restrict__ clo)
{
    extern __shared__ char smem[];
    const int tid = threadIdx.x, wid = tid >> 5, lane = tid & 31;
    const int qq = lane >> 3, rr = lane & 7;
    const int qt = 15 - blockIdx.x;           // heavy CTAs first
    const int bh = blockIdx.y, b = bh >> 4, h = bh & 15;
    const int q0 = qt * 128;
    const size_t qkbase = (size_t)b * S_ * DIM_ + h * HD_;
    const size_t vbase  = (size_t)bh * 64 * S_;
    const uint32_t sb = smem_u32(smem);
    const uint32_t QHI = 0, QLO = QTB, ST0 = 2 * QTB;

#pragma unroll
    for (int t = 0; t < 8; t++) {
        const int idx = tid + t * 256;
        const int op = idx >> 10;
        const int r = (idx >> 3) & 127, c = idx & 7;
        const __nv_bfloat16* src = (op ? qlo : qhi) + qkbase + (size_t)(q0 + r) * DIM_ + c * 8;
        cp16(sb + (op ? QLO : QHI) + r * FROW + c * 16, src);
    }

    auto load_kv = [&](int kt) {
        const uint32_t d0 = sb + ST0 + (kt & 1) * FSTAGE;
        const int k0 = kt * 64;
#pragma unroll
        for (int t = 0; t < 8; t++) {
            const int idx = tid + t * 256;
            const int which = idx >> 9;
            const int r = (idx >> 3) & 63, c = idx & 7;
            const uint32_t dst = d0 + which * KTB + r * FROW + c * 16;
            const __nv_bfloat16* src;
            if (which == 0)      src = khi  + qkbase + (size_t)(k0 + r) * DIM_ + c * 8;
            else if (which == 1) src = klo  + qkbase + (size_t)(k0 + r) * DIM_ + c * 8;
            else if (which == 2) src = vhiT + vbase + (size_t)r * S_ + k0 + c * 8;
            else                 src = vloT + vbase + (size_t)r * S_ + k0 + c * 8;
            cp16(dst, src);
        }
    };
    load_kv(0); CP_COMMIT();

    float m[2] = {-1e30f, -1e30f}, l[2] = {0.f, 0.f};
    float oacc[8][4];
#pragma unroll
    for (int nt = 0; nt < 8; nt++)
#pragma unroll
        for (int c = 0; c < 4; c++) oacc[nt][c] = 0.f;

    const int rowlo = q0 + wid * 16 + (lane >> 2);
    const int nkt = 2 * (qt + 1);

    for (int kt = 0; kt < nkt; kt++) {
        if (kt + 1 < nkt) { load_kv(kt + 1); CP_COMMIT(); CP_WAIT(1); }
        else              { CP_WAIT(0); }
        __syncthreads();

        const int k0 = kt * 64;
        const bool active = (k0 <= q0 + wid * 16 + 15);
        if (active) {
            const uint32_t kb = sb + ST0 + (kt & 1) * FSTAGE;

            float sacc[8][4];
#pragma unroll
            for (int nt = 0; nt < 8; nt++)
#pragma unroll
                for (int c = 0; c < 4; c++) sacc[nt][c] = 0.f;

#pragma unroll
            for (int kk = 0; kk < 4; kk++) {
                uint32_t aqh[4], aql[4];
                const uint32_t aoff = (wid * 16 + (qq & 1) * 8 + rr) * FROW
                                    + (2 * kk + (qq >> 1)) * 16;
                ldsm_x4(aqh, sb + QHI + aoff);
                ldsm_x4(aql, sb + QLO + aoff);
#pragma unroll
                for (int np = 0; np < 4; np++) {
                    const uint32_t boff = (np * 16 + (qq >> 1) * 8 + rr) * FROW
                                        + (2 * kk + (qq & 1)) * 16;
                    uint32_t th[4], tl[4];
                    ldsm_x4(th, kb + boff);
                    ldsm_x4(tl, kb + KTB + boff);
                    mma16816(sacc[2 * np],     aqh, &th[0]);
                    mma16816(sacc[2 * np + 1], aqh, &th[2]);
                    mma16816(sacc[2 * np],     aqh, &tl[0]);
                    mma16816(sacc[2 * np + 1], aqh, &tl[2]);
                    mma16816(sacc[2 * np],     aql, &th[0]);
                    mma16816(sacc[2 * np + 1], aql, &th[2]);
                }
            }

            if (k0 + 63 > q0 + wid * 16) {
#pragma unroll
                for (int nt = 0; nt < 8; nt++)
#pragma unroll
                    for (int c = 0; c < 4; c++) {
                        const int gcol = k0 + nt * 8 + (lane & 3) * 2 + (c & 1);
                        const int grow = rowlo + ((c >> 1) << 3);
                        if (gcol > grow) sacc[nt][c] = -1e30f;
                    }
            }

            float corr[2];
#pragma unroll
            for (int hh = 0; hh < 2; hh++) {
                float rmax = -1e30f;
#pragma unroll
                for (int nt = 0; nt < 8; nt++)
                    rmax = fmaxf(rmax, fmaxf(sacc[nt][2 * hh], sacc[nt][2 * hh + 1]));
                rmax = fmaxf(rmax, __shfl_xor_sync(0xffffffffu, rmax, 1));
                rmax = fmaxf(rmax, __shfl_xor_sync(0xffffffffu, rmax, 2));
                const float mnew = fmaxf(m[hh], rmax);
                corr[hh] = exp2f(m[hh] - mnew);
                m[hh] = mnew;
                float rsum = 0.f;
#pragma unroll
                for (int nt = 0; nt < 8; nt++) {
                    float p0 = exp2f(sacc[nt][2 * hh]     - mnew);
                    float p1 = exp2f(sacc[nt][2 * hh + 1] - mnew);
                    sacc[nt][2 * hh] = p0; sacc[nt][2 * hh + 1] = p1;
                    rsum += p0 + p1;
                }
                rsum += __shfl_xor_sync(0xffffffffu, rsum, 1);
                rsum += __shfl_xor_sync(0xffffffffu, rsum, 2);
                l[hh] = l[hh] * corr[hh] + rsum;
#pragma unroll
                for (int nt = 0; nt < 8; nt++) {
                    oacc[nt][2 * hh]     *= corr[hh];
                    oacc[nt][2 * hh + 1] *= corr[hh];
                }
            }

#pragma unroll
            for (int kk = 0; kk < 4; kk++) {
                uint32_t ph[4], pl[4];
                pack_hl(ph[0], pl[0], sacc[2 * kk][0],     sacc[2 * kk][1]);
                pack_hl(ph[1], pl[1], sacc[2 * kk][2],     sacc[2 * kk][3]);
                pack_hl(ph[2], pl[2], sacc[2 * kk + 1][0], sacc[2 * kk + 1][1]);
                pack_hl(ph[3], pl[3], sacc[2 * kk + 1][2], sacc[2 * kk + 1][3]);
#pragma unroll
                for (int np = 0; np < 4; np++) {
                    const uint32_t boff = (np * 16 + (qq >> 1) * 8 + rr) * FROW
                                        + (2 * kk + (qq & 1)) * 16;
                    uint32_t th[4], tl[4];
                    ldsm_x4(th, kb + 2 * KTB + boff);
                    ldsm_x4(tl, kb + 3 * KTB + boff);
                    mma16816(oacc[2 * np],     ph, &th[0]);
                    mma16816(oacc[2 * np + 1], ph, &th[2]);
                    mma16816(oacc[2 * np],     ph, &tl[0]);
                    mma16816(oacc[2 * np + 1], ph, &tl[2]);
                    mma16816(oacc[2 * np],     pl, &th[0]);
                    mma16816(oacc[2 * np + 1], pl, &th[2]);
                }
            }
        }
        __syncthreads();
    }

    const float inv0 = 1.f / l[0], inv1 = 1.f / l[1];
#pragma unroll
    for (int nt = 0; nt < 8; nt++) {
#pragma unroll
        for (int hh = 0; hh < 2; hh++) {
            const float inv = hh ? inv1 : inv0;
            const int row = rowlo + 8 * hh;
            const size_t off = ((size_t)b * S_ + row) * DIM_ + h * HD_
                             + nt * 8 + (lane & 3) * 2;
            uint32_t ph, pl;
            pack_hl(ph, pl, oacc[nt][2 * hh] * inv, oacc[nt][2 * hh + 1] * inv);
            *(uint32_t*)(chi + off) = ph;
            *(uint32_t*)(clo + off) = pl;
        }
    }
}

// ---------------------------------------------------------------------------
extern "C" void kernel_launch(void* const* d_in, const int* in_sizes, int n_in,
                              void* d_out, int out_size)
{
    (void)in_sizes; (void)n_in; (void)out_size;
    const float* x  = (const float*)d_in[0];
    const float* Wq = (const float*)d_in[1];
    const float* Wk = (const float*)d_in[2];
    const float* Wv = (const float*)d_in[3];
    const float* Wo = (const float*)d_in[4];
    float* out = (float*)d_out;

    __nv_bfloat16 *xhi, *xlo, *chi, *clo, *whi, *wlo;
    __nv_bfloat16 *qhi, *qlo, *khi, *klo, *vThi, *vTlo;
    float2* rtab;
    cudaGetSymbolAddress((void**)&xhi,  g_xhi);
    cudaGetSymbolAddress((void**)&xlo,  g_xlo);
    cudaGetSymbolAddress((void**)&chi,  g_chi);
    cudaGetSymbolAddress((void**)&clo,  g_clo);
    cudaGetSymbolAddress((void**)&whi,  g_whi);
    cudaGetSymbolAddress((void**)&wlo,  g_wlo);
    cudaGetSymbolAddress((void**)&qhi,  g_qhi);
    cudaGetSymbolAddress((void**)&qlo,  g_qlo);
    cudaGetSymbolAddress((void**)&khi,  g_khi);
    cudaGetSymbolAddress((void**)&klo,  g_klo);
    cudaGetSymbolAddress((void**)&vThi, g_vThi);
    cudaGetSymbolAddress((void**)&vTlo, g_vTlo);
    cudaGetSymbolAddress((void**)&rtab, g_rtab);

    cudaFuncSetAttribute(gemm_bf16x3, cudaFuncAttributeMaxDynamicSharedMemorySize, GSMEM);
    cudaFuncSetAttribute(flash_mma,  cudaFuncAttributeMaxDynamicSharedMemorySize, FSMEM);

    // Launch order (profiled launch = global index 3):
    //   split(0), rope(1), gemmQKV(2), flash(3) <- profiled, gemmO(4)
    split_all<<<(TOT_N4 + 255) / 256, 256>>>(x, Wq, Wk, Wv, Wo,
                                             xhi, xlo, whi, wlo);
    rope_tab<<<256, 256>>>(rtab);

    // Q/K/V projections with fused RoPE/split/transpose epilogues
    {
        dim3 grid(DIM_ / 256, MROWS / 128, 3), block(256);
        gemm_bf16x3<<<grid, block, GSMEM>>>(xhi, xlo, whi, wlo,
                                            nullptr, 1, rtab,
                                            qhi, qlo, khi, klo, vThi, vTlo);
    }
    // flash attention on tensor cores -> chi/clo
    {
        dim3 grid(16, B_ * H_), block(256);
        flash_mma<<<grid, block, FSMEM>>>(qhi, qlo, khi, klo, vThi, vTlo, chi, clo);
    }
    // output projection (plain epilogue)
    {
        dim3 grid(DIM_ / 256, MROWS / 128, 1), block(256);
        gemm_bf16x3<<<grid, block, GSMEM>>>(chi, clo, whi + 3 * (size_t)NK, wlo + 3 * (size_t)NK,
                                            out, 0, rtab,
                                            qhi, qlo, khi, klo, vThi, vTlo);
    }
}

// round 16
// speedup vs baseline: 1.0486x; 1.0486x over previous
#include <cuda_runtime.h>
#include <cuda_bf16.h>
#include <math.h>
#include <cstdint>

#define B_    4
#define S_    2048
#define DIM_  1024
#define H_    16
#define HD_   64
#define BSD   (B_ * S_ * DIM_)     // 8,388,608
#define MROWS (B_ * S_)            // 8192
#define NK    (DIM_ * DIM_)        // 1,048,576

// ---------------- device scratch (no cudaMalloc allowed) -------------------
__device__ __nv_bfloat16 g_xhi[BSD], g_xlo[BSD];
__device__ __nv_bfloat16 g_chi[BSD], g_clo[BSD];
__device__ __nv_bfloat16 g_whi[4 * NK], g_wlo[4 * NK];
__device__ __nv_bfloat16 g_qhi[BSD], g_qlo[BSD];
__device__ __nv_bfloat16 g_khi[BSD], g_klo[BSD];
__device__ __nv_bfloat16 g_vThi[BSD], g_vTlo[BSD];   // layout (b,h,d,s)
__device__ float2 g_rtab[S_ * 32];

// ---------------- PTX helpers (sm_80+ only; NO a-suffix features) ----------
__device__ __forceinline__ uint32_t smem_u32(const void* p) {
    uint32_t a;
    asm("{ .reg .u64 t; cvta.to.shared.u64 t, %1; cvt.u32.u64 %0, t; }"
        : "=r"(a) : "l"(p));
    return a;
}
__device__ __forceinline__ void cp16(uint32_t dst, const void* src) {
    asm volatile("cp.async.cg.shared.global [%0], [%1], 16;"
                 :: "r"(dst), "l"(src));
}
#define CP_COMMIT() asm volatile("cp.async.commit_group;" ::: "memory")
#define CP_WAIT(n)  asm volatile("cp.async.wait_group %0;" :: "n"(n) : "memory")

__device__ __forceinline__ void ldsm_x4(uint32_t* r, uint32_t addr) {
    asm volatile("ldmatrix.sync.aligned.m8n8.x4.shared.b16 {%0,%1,%2,%3}, [%4];"
                 : "=r"(r[0]), "=r"(r[1]), "=r"(r[2]), "=r"(r[3]) : "r"(addr));
}
__device__ __forceinline__ void mma16816(float* c, const uint32_t* a, const uint32_t* b) {
    asm volatile(
        "mma.sync.aligned.m16n8k16.row.col.f32.bf16.bf16.f32 "
        "{%0,%1,%2,%3}, {%4,%5,%6,%7}, {%8,%9}, {%0,%1,%2,%3};"
        : "+f"(c[0]), "+f"(c[1]), "+f"(c[2]), "+f"(c[3])
        : "r"(a[0]), "r"(a[1]), "r"(a[2]), "r"(a[3]), "r"(b[0]), "r"(b[1]));
}

__device__ __forceinline__ void pack_hl(uint32_t& ph, uint32_t& pl, float a, float b) {
    __nv_bfloat162 hb = __floats2bfloat162_rn(a, b);
    float2 hf = __bfloat1622float2(hb);
    __nv_bfloat162 lb = __floats2bfloat162_rn(a - hf.x, b - hf.y);
    ph = reinterpret_cast<uint32_t&>(hb);
    pl = reinterpret_cast<uint32_t&>(lb);
}

// ---------------------------------------------------------------------------
// fused split + rope table: blocks [0, SPLIT_BLKS) split x + 4 weights to
// bf16 hi/lo; blocks [SPLIT_BLKS, SPLIT_BLKS+256) build the fp64-accurate
// RoPE table (identical math/values to the former rope_tab kernel).
// ---------------------------------------------------------------------------
#define X_N4 (BSD / 4)    // 2,097,152
#define W_N4 (NK / 4)     // 262,144
#define TOT_N4 (X_N4 + 4 * W_N4)
#define SPLIT_BLKS ((TOT_N4 + 255) / 256)   // 12288

__global__ __launch_bounds__(256) void split_all(
    const float* __restrict__ x,
    const float* __restrict__ W0, const float* __restrict__ W1,
    const float* __restrict__ W2, const float* __restrict__ W3,
    __nv_bfloat16* __restrict__ xhi, __nv_bfloat16* __restrict__ xlo,
    __nv_bfloat16* __restrict__ whi, __nv_bfloat16* __restrict__ wlo,
    float2* __restrict__ tab)
{
    if (blockIdx.x >= SPLIT_BLKS) {
        // rope-table part
        const int idx = (blockIdx.x - SPLIT_BLKS) * 256 + threadIdx.x; // 0..65535
        const int s = idx >> 5;
        const int i = idx & 31;
        const double inv = exp(-((double)(2 * i) / 64.0) * 9.210340371976184);
        double ang = (double)s * inv;
        const double tp = 6.283185307179586476925287;
        ang -= floor(ang / tp) * tp;
        tab[s * 32 + i] = make_float2((float)cos(ang), (float)sin(ang));
        return;
    }

    const int i = blockIdx.x * blockDim.x + threadIdx.x;
    if (i >= TOT_N4) return;

    const float* src;
    __nv_bfloat16 *hi, *lo;
    int j;
    if (i < X_N4) {
        src = x; hi = xhi; lo = xlo; j = i;
    } else {
        const int wi = i - X_N4;
        const int w = wi >> 18;            // /262144
        j = wi & (W_N4 - 1);
        src = (w == 0) ? W0 : (w == 1) ? W1 : (w == 2) ? W2 : W3;
        hi = whi + (size_t)w * NK;
        lo = wlo + (size_t)w * NK;
    }

    float4 v = ((const float4*)src)[j];
    __nv_bfloat16 h0 = __float2bfloat16(v.x);
    __nv_bfloat16 h1 = __float2bfloat16(v.y);
    __nv_bfloat16 h2 = __float2bfloat16(v.z);
    __nv_bfloat16 h3 = __float2bfloat16(v.w);
    __nv_bfloat16 l0 = __float2bfloat16(v.x - __bfloat162float(h0));
    __nv_bfloat16 l1 = __float2bfloat16(v.y - __bfloat162float(h1));
    __nv_bfloat16 l2 = __float2bfloat16(v.z - __bfloat162float(h2));
    __nv_bfloat16 l3 = __float2bfloat16(v.w - __bfloat162float(h3));
    __nv_bfloat162* hp = (__nv_bfloat162*)(hi + (size_t)j * 4);
    __nv_bfloat162* lp = (__nv_bfloat162*)(lo + (size_t)j * 4);
    hp[0] = __nv_bfloat162(h0, h1); hp[1] = __nv_bfloat162(h2, h3);
    lp[0] = __nv_bfloat162(l0, l1); lp[1] = __nv_bfloat162(l2, l3);
}

// ---------------------------------------------------------------------------
// mma.sync bf16x3-compensated GEMM — FROZEN R14 configuration (measured
// optimum over 7 variants): CTA 128x128, BK=32, 8 warps (2x4), 3-stage
// cp.async with register-rotated bases, ONE barrier/iter, 2 CTAs/SM.
// INVARIANT (R7, R13, R15): prefetch AFTER compute; 2 CTAs/SM mandatory.
// fused=1 (QKV): RoPE/split/transpose epilogues. fused=0 (O): plain fp32.
// q is pre-scaled by 0.125*log2(e) so flash softmax can use exp2 directly.
// ---------------------------------------------------------------------------
#define BK     32
#define NITER  (DIM_ / BK)
#define ATILE  16384                // 128 rows * 128B
#define STAGEB (2 * ATILE)          // A + B = 32768
#define FT_PITCH 130
#define GSMEM  (3 * STAGEB)         // 98304 (FT epilogue needs 66560, fits)
#define QSCALE 0.18033688011112042f // 0.125 * log2(e)

__global__ __launch_bounds__(256, 2) void gemm_bf16x3(
    const __nv_bfloat16* __restrict__ Ahi, const __nv_bfloat16* __restrict__ Alo,
    const __nv_bfloat16* __restrict__ Whi, const __nv_bfloat16* __restrict__ Wlo,
    float* __restrict__ C0,
    int fused,
    const float2* __restrict__ rtab,
    __nv_bfloat16* __restrict__ qhi, __nv_bfloat16* __restrict__ qlo,
    __nv_bfloat16* __restrict__ khi, __nv_bfloat16* __restrict__ klo,
    __nv_bfloat16* __restrict__ vThi, __nv_bfloat16* __restrict__ vTlo)
{
    extern __shared__ char smem[];
    const int tid  = threadIdx.x;
    const int wid  = tid >> 5;
    const int lane = tid & 31;
    const int qq   = lane >> 3;
    const int rr   = lane & 7;
    const int wm   = wid >> 2;
    const int wn   = wid & 3;
    const int z    = blockIdx.z;

    const __nv_bfloat16* Wh = Whi + (size_t)z * NK;
    const __nv_bfloat16* Wl = Wlo + (size_t)z * NK;

    const int m0 = blockIdx.y * 128;
    const int n0 = blockIdx.x * 128;
    const uint32_t sb = smem_u32(smem);

    float acc[4][4][4];
#pragma unroll
    for (int a = 0; a < 4; a++)
#pragma unroll
        for (int b = 0; b < 4; b++)
#pragma unroll
            for (int c = 0; c < 4; c++) acc[a][b][c] = 0.f;

    auto load_stage = [&](uint32_t dbase, int kc) {
#pragma unroll
        for (int t = 0; t < 4; t++) {
            const int idx = tid + t * 256;          // 0..1023
            const int r = idx >> 3, c = idx & 7;    // c: 0-3 hi, 4-7 lo
            const uint32_t doff = r * 128 + ((c ^ (r & 7)) << 4);
            const size_t goff = (size_t)r * DIM_ + kc + (c & 3) * 8;
            const __nv_bfloat16* srcA = (c < 4 ? Ahi : Alo) + (size_t)m0 * DIM_ + goff;
            const __nv_bfloat16* srcB = (c < 4 ? Wh  : Wl ) + (size_t)n0 * DIM_ + goff;
            cp16(dbase + doff,         srcA);
            cp16(dbase + ATILE + doff, srcB);
        }
        CP_COMMIT();
    };

    uint32_t buf0 = sb;
    uint32_t buf1 = sb + STAGEB;
    uint32_t buf2 = sb + 2 * STAGEB;

    load_stage(buf0, 0);
    load_stage(buf1, BK);

    for (int it = 0; it < NITER; it++) {
        if (it + 1 < NITER) CP_WAIT(1);
        else                CP_WAIT(0);
        __syncthreads();

        const uint32_t abase = buf0;
        const uint32_t bbase = buf0 + ATILE;

#pragma unroll
        for (int ks = 0; ks < 2; ks++) {
            uint32_t bh[4][2], bl[4][2];
            const int bch = 2 * ks + (qq & 1);
#pragma unroll
            for (int np = 0; np < 2; np++) {
                const int brow = wn * 32 + np * 16 + (qq >> 1) * 8 + rr;
                const uint32_t sw = brow * 128;
                uint32_t t[4];
                ldsm_x4(t, bbase + sw + ((bch ^ (brow & 7)) << 4));
                bh[2 * np][0] = t[0]; bh[2 * np][1] = t[1];
                bh[2 * np + 1][0] = t[2]; bh[2 * np + 1][1] = t[3];
                ldsm_x4(t, bbase + sw + (((bch + 4) ^ (brow & 7)) << 4));
                bl[2 * np][0] = t[0]; bl[2 * np][1] = t[1];
                bl[2 * np + 1][0] = t[2]; bl[2 * np + 1][1] = t[3];
            }
            const int ach = 2 * ks + (qq >> 1);
#pragma unroll
            for (int mt = 0; mt < 4; mt++) {
                const int arow = wm * 64 + mt * 16 + (qq & 1) * 8 + rr;
                const uint32_t sw = arow * 128;
                uint32_t ah[4], al[4];
                ldsm_x4(ah, abase + sw + ((ach ^ (arow & 7)) << 4));
                ldsm_x4(al, abase + sw + (((ach + 4) ^ (arow & 7)) << 4));
#pragma unroll
                for (int nt = 0; nt < 4; nt++) mma16816(acc[mt][nt], ah, bh[nt]);
#pragma unroll
                for (int nt = 0; nt < 4; nt++) mma16816(acc[mt][nt], ah, bl[nt]);
#pragma unroll
                for (int nt = 0; nt < 4; nt++) mma16816(acc[mt][nt], al, bh[nt]);
            }
        }

        // prefetch stage it+2 AFTER compute (invariant)
        if (it + 2 < NITER)
            load_stage(buf2, (it + 2) * BK);

        const uint32_t tmp = buf0; buf0 = buf1; buf1 = buf2; buf2 = tmp;
    }

    if (!fused) {
#pragma unroll
        for (int mt = 0; mt < 4; mt++)
#pragma unroll
            for (int nt = 0; nt < 4; nt++) {
                const int row = m0 + wm * 64 + mt * 16 + (lane >> 2);
                const int col = n0 + wn * 32 + nt * 8 + (lane & 3) * 2;
                *(float2*)&C0[(size_t)row * DIM_ + col] =
                    make_float2(acc[mt][nt][0], acc[mt][nt][1]);
                *(float2*)&C0[(size_t)(row + 8) * DIM_ + col] =
                    make_float2(acc[mt][nt][2], acc[mt][nt][3]);
            }
        return;
    }

    // ---- fused epilogue: stage fp32 tile in smem (stage buffers are dead) ----
    __syncthreads();
    float* ft = (float*)smem;
#define FT(r, c) ft[(r) * FT_PITCH + (c)]
#pragma unroll
    for (int mt = 0; mt < 4; mt++)
#pragma unroll
        for (int nt = 0; nt < 4; nt++) {
            const int r = wm * 64 + mt * 16 + (lane >> 2);
            const int c = wn * 32 + nt * 8 + (lane & 3) * 2;
            FT(r, c)     = acc[mt][nt][0];
            FT(r, c + 1) = acc[mt][nt][1];
            FT(r + 8, c)     = acc[mt][nt][2];
            FT(r + 8, c + 1) = acc[mt][nt][3];
        }
    __syncthreads();

    if (z < 2) {
        const int r  = tid >> 1;
        const int g  = tid & 1;
        const int m  = m0 + r;
        const int ss = m & (S_ - 1);
        const float scale = (z == 0) ? QSCALE : 1.0f;
        __nv_bfloat16* dh = (z == 0) ? qhi : khi;
        __nv_bfloat16* dl = (z == 0) ? qlo : klo;
        const size_t dst = (size_t)m * DIM_ + n0 + g * 64;
        const float2* trow = rtab + ss * 32;
#pragma unroll
        for (int dc = 0; dc < 32; dc += 8) {
            uint32_t h1[4], l1[4], h2[4], l2[4];
#pragma unroll
            for (int j = 0; j < 4; j++) {
                const int d0 = dc + 2 * j;
                const float2 cs0 = trow[d0];
                const float2 cs1 = trow[d0 + 1];
                const float x1 = FT(r, g * 64 + d0);
                const float x2 = FT(r, g * 64 + d0 + 32);
                const float y1 = FT(r, g * 64 + d0 + 1);
                const float y2 = FT(r, g * 64 + d0 + 33);
                const float o1 = (x1 * cs0.x - x2 * cs0.y) * scale;
                const float o2 = (x2 * cs0.x + x1 * cs0.y) * scale;
                const float p1 = (y1 * cs1.x - y2 * cs1.y) * scale;
                const float p2 = (y2 * cs1.x + y1 * cs1.y) * scale;
                pack_hl(h1[j], l1[j], o1, p1);
                pack_hl(h2[j], l2[j], o2, p2);
            }
            *(uint4*)(dh + dst + dc)      = make_uint4(h1[0], h1[1], h1[2], h1[3]);
            *(uint4*)(dh + dst + dc + 32) = make_uint4(h2[0], h2[1], h2[2], h2[3]);
            *(uint4*)(dl + dst + dc)      = make_uint4(l1[0], l1[1], l1[2], l1[3]);
            *(uint4*)(dl + dst + dc + 32) = make_uint4(l2[0], l2[1], l2[2], l2[3]);
        }
    } else {
        const int col = tid >> 1;           // 0..127
        const int sh  = tid & 1;
        const int gcol = n0 + col;
        const int h   = gcol >> 6, d = gcol & 63;
        const int bb  = m0 >> 11, s0loc = (m0 & (S_ - 1)) + sh * 64;
        const size_t dst = (((size_t)(bb * H_ + h)) * HD_ + d) * S_ + s0loc;
#pragma unroll
        for (int sc = 0; sc < 64; sc += 8) {
            uint32_t hh[4], ll[4];
#pragma unroll
            for (int j = 0; j < 4; j++) {
                const int srow = sh * 64 + sc + 2 * j;
                pack_hl(hh[j], ll[j], FT(srow, col), FT(srow + 1, col));
            }
            *(uint4*)(vThi + dst + sc) = make_uint4(hh[0], hh[1], hh[2], hh[3]);
            *(uint4*)(vTlo + dst + sc) = make_uint4(ll[0], ll[1], ll[2], ll[3]);
        }
    }
#undef FT
}

// ---------------------------------------------------------------------------
// Flash attention on mma.sync bf16x3 (frozen at R14 state).
// ---------------------------------------------------------------------------
#define FROW   144                      // 64 bf16 = 128B + 16B pad
#define QTB    (128 * FROW)             // 18432
#define KTB    (64 * FROW)              // 9216
#define FSTAGE (4 * KTB)                // 36864: khi,klo,vhi,vlo
#define FSMEM  (2 * QTB + 2 * FSTAGE)   // 110592

__global__ __launch_bounds__(256, 2) void flash_mma(
    const __nv_bfloat16* __restrict__ qhi, const __nv_bfloat16* __restrict__ qlo,
    const __nv_bfloat16* __restrict__ khi, const __nv_bfloat16* __restrict__ klo,
    const __nv_bfloat16* __restrict__ vhiT, const __nv_bfloat16* __restrict__ vloT,
    __nv_bfloat16* __restrict__ chi, __nv_bfloat16* __restrict__ clo)
{
    extern __shared__ char smem[];
    const int tid = threadIdx.x, wid = tid >> 5, lane = tid & 31;
    const int qq = lane >> 3, rr = lane & 7;
    const int qt = 15 - blockIdx.x;           // heavy CTAs first
    const int bh = blockIdx.y, b = bh >> 4, h = bh & 15;
    const int q0 = qt * 128;
    const size_t qkbase = (size_t)b * S_ * DIM_ + h * HD_;
    const size_t vbase  = (size_t)bh * 64 * S_;
    const uint32_t sb = smem_u32(smem);
    const uint32_t QHI = 0, QLO = QTB, ST0 = 2 * QTB;

#pragma unroll
    for (int t = 0; t < 8; t++) {
        const int idx = tid + t * 256;
        const int op = idx >> 10;
        const int r = (idx >> 3) & 127, c = idx & 7;
        const __nv_bfloat16* src = (op ? qlo : qhi) + qkbase + (size_t)(q0 + r) * DIM_ + c * 8;
        cp16(sb + (op ? QLO : QHI) + r * FROW + c * 16, src);
    }

    auto load_kv = [&](int kt) {
        const uint32_t d0 = sb + ST0 + (kt & 1) * FSTAGE;
        const int k0 = kt * 64;
#pragma unroll
        for (int t = 0; t < 8; t++) {
            const int idx = tid + t * 256;
            const int which = idx >> 9;
            const int r = (idx >> 3) & 63, c = idx & 7;
            const uint32_t dst = d0 + which * KTB + r * FROW + c * 16;
            const __nv_bfloat16* src;
            if (which == 0)      src = khi  + qkbase + (size_t)(k0 + r) * DIM_ + c * 8;
            else if (which == 1) src = klo  + qkbase + (size_t)(k0 + r) * DIM_ + c * 8;
            else if (which == 2) src = vhiT + vbase + (size_t)r * S_ + k0 + c * 8;
            else                 src = vloT + vbase + (size_t)r * S_ + k0 + c * 8;
            cp16(dst, src);
        }
    };
    load_kv(0); CP_COMMIT();

    float m[2] = {-1e30f, -1e30f}, l[2] = {0.f, 0.f};
    float oacc[8][4];
#pragma unroll
    for (int nt = 0; nt < 8; nt++)
#pragma unroll
        for (int c = 0; c < 4; c++) oacc[nt][c] = 0.f;

    const int rowlo = q0 + wid * 16 + (lane >> 2);
    const int nkt = 2 * (qt + 1);

    for (int kt = 0; kt < nkt; kt++) {
        if (kt + 1 < nkt) { load_kv(kt + 1); CP_COMMIT(); CP_WAIT(1); }
        else              { CP_WAIT(0); }
        __syncthreads();

        const int k0 = kt * 64;
        const bool active = (k0 <= q0 + wid * 16 + 15);
        if (active) {
            const uint32_t kb = sb + ST0 + (kt & 1) * FSTAGE;

            float sacc[8][4];
#pragma unroll
            for (int nt = 0; nt < 8; nt++)
#pragma unroll
                for (int c = 0; c < 4; c++) sacc[nt][c] = 0.f;

#pragma unroll
            for (int kk = 0; kk < 4; kk++) {
                uint32_t aqh[4], aql[4];
                const uint32_t aoff = (wid * 16 + (qq & 1) * 8 + rr) * FROW
                                    + (2 * kk + (qq >> 1)) * 16;
                ldsm_x4(aqh, sb + QHI + aoff);
                ldsm_x4(aql, sb + QLO + aoff);
#pragma unroll
                for (int np = 0; np < 4; np++) {
                    const uint32_t boff = (np * 16 + (qq >> 1) * 8 + rr) * FROW
                                        + (2 * kk + (qq & 1)) * 16;
                    uint32_t th[4], tl[4];
                    ldsm_x4(th, kb + boff);
                    ldsm_x4(tl, kb + KTB + boff);
                    mma16816(sacc[2 * np],     aqh, &th[0]);
                    mma16816(sacc[2 * np + 1], aqh, &th[2]);
                    mma16816(sacc[2 * np],     aqh, &tl[0]);
                    mma16816(sacc[2 * np + 1], aqh, &tl[2]);
                    mma16816(sacc[2 * np],     aql, &th[0]);
                    mma16816(sacc[2 * np + 1], aql, &th[2]);
                }
            }

            if (k0 + 63 > q0 + wid * 16) {
#pragma unroll
                for (int nt = 0; nt < 8; nt++)
#pragma unroll
                    for (int c = 0; c < 4; c++) {
                        const int gcol = k0 + nt * 8 + (lane & 3) * 2 + (c & 1);
                        const int grow = rowlo + ((c >> 1) << 3);
                        if (gcol > grow) sacc[nt][c] = -1e30f;
                    }
            }

            float corr[2];
#pragma unroll
            for (int hh = 0; hh < 2; hh++) {
                float rmax = -1e30f;
#pragma unroll
                for (int nt = 0; nt < 8; nt++)
                    rmax = fmaxf(rmax, fmaxf(sacc[nt][2 * hh], sacc[nt][2 * hh + 1]));
                rmax = fmaxf(rmax, __shfl_xor_sync(0xffffffffu, rmax, 1));
                rmax = fmaxf(rmax, __shfl_xor_sync(0xffffffffu, rmax, 2));
                const float mnew = fmaxf(m[hh], rmax);
                corr[hh] = exp2f(m[hh] - mnew);
                m[hh] = mnew;
                float rsum = 0.f;
#pragma unroll
                for (int nt = 0; nt < 8; nt++) {
                    float p0 = exp2f(sacc[nt][2 * hh]     - mnew);
                    float p1 = exp2f(sacc[nt][2 * hh + 1] - mnew);
                    sacc[nt][2 * hh] = p0; sacc[nt][2 * hh + 1] = p1;
                    rsum += p0 + p1;
                }
                rsum += __shfl_xor_sync(0xffffffffu, rsum, 1);
                rsum += __shfl_xor_sync(0xffffffffu, rsum, 2);
                l[hh] = l[hh] * corr[hh] + rsum;
#pragma unroll
                for (int nt = 0; nt < 8; nt++) {
                    oacc[nt][2 * hh]     *= corr[hh];
                    oacc[nt][2 * hh + 1] *= corr[hh];
                }
            }

#pragma unroll
            for (int kk = 0; kk < 4; kk++) {
                uint32_t ph[4], pl[4];
                pack_hl(ph[0], pl[0], sacc[2 * kk][0],     sacc[2 * kk][1]);
                pack_hl(ph[1], pl[1], sacc[2 * kk][2],     sacc[2 * kk][3]);
                pack_hl(ph[2], pl[2], sacc[2 * kk + 1][0], sacc[2 * kk + 1][1]);
                pack_hl(ph[3], pl[3], sacc[2 * kk + 1][2], sacc[2 * kk + 1][3]);
#pragma unroll
                for (int np = 0; np < 4; np++) {
                    const uint32_t boff = (np * 16 + (qq >> 1) * 8 + rr) * FROW
                                        + (2 * kk + (qq & 1)) * 16;
                    uint32_t th[4], tl[4];
                    ldsm_x4(th, kb + 2 * KTB + boff);
                    ldsm_x4(tl, kb + 3 * KTB + boff);
                    mma16816(oacc[2 * np],     ph, &th[0]);
                    mma16816(oacc[2 * np + 1], ph, &th[2]);
                    mma16816(oacc[2 * np],     ph, &tl[0]);
                    mma16816(oacc[2 * np + 1], ph, &tl[2]);
                    mma16816(oacc[2 * np],     pl, &th[0]);
                    mma16816(oacc[2 * np + 1], pl, &th[2]);
                }
            }
        }
        __syncthreads();
    }

    const float inv0 = 1.f / l[0], inv1 = 1.f / l[1];
#pragma unroll
    for (int nt = 0; nt < 8; nt++) {
#pragma unroll
        for (int hh = 0; hh < 2; hh++) {
            const float inv = hh ? inv1 : inv0;
            const int row = rowlo + 8 * hh;
            const size_t off = ((size_t)b * S_ + row) * DIM_ + h * HD_
                             + nt * 8 + (lane & 3) * 2;
            uint32_t ph, pl;
            pack_hl(ph, pl, oacc[nt][2 * hh] * inv, oacc[nt][2 * hh + 1] * inv);
            *(uint32_t*)(chi + off) = ph;
            *(uint32_t*)(clo + off) = pl;
        }
    }
}

// ---------------------------------------------------------------------------
extern "C" void kernel_launch(void* const* d_in, const int* in_sizes, int n_in,
                              void* d_out, int out_size)
{
    (void)in_sizes; (void)n_in; (void)out_size;
    const float* x  = (const float*)d_in[0];
    const float* Wq = (const float*)d_in[1];
    const float* Wk = (const float*)d_in[2];
    const float* Wv = (const float*)d_in[3];
    const float* Wo = (const float*)d_in[4];
    float* out = (float*)d_out;

    __nv_bfloat16 *xhi, *xlo, *chi, *clo, *whi, *wlo;
    __nv_bfloat16 *qhi, *qlo, *khi, *klo, *vThi, *vTlo;
    float2* rtab;
    cudaGetSymbolAddress((void**)&xhi,  g_xhi);
    cudaGetSymbolAddress((void**)&xlo,  g_xlo);
    cudaGetSymbolAddress((void**)&chi,  g_chi);
    cudaGetSymbolAddress((void**)&clo,  g_clo);
    cudaGetSymbolAddress((void**)&whi,  g_whi);
    cudaGetSymbolAddress((void**)&wlo,  g_wlo);
    cudaGetSymbolAddress((void**)&qhi,  g_qhi);
    cudaGetSymbolAddress((void**)&qlo,  g_qlo);
    cudaGetSymbolAddress((void**)&khi,  g_khi);
    cudaGetSymbolAddress((void**)&klo,  g_klo);
    cudaGetSymbolAddress((void**)&vThi, g_vThi);
    cudaGetSymbolAddress((void**)&vTlo, g_vTlo);
    cudaGetSymbolAddress((void**)&rtab, g_rtab);

    cudaFuncSetAttribute(gemm_bf16x3, cudaFuncAttributeMaxDynamicSharedMemorySize, GSMEM);
    cudaFuncSetAttribute(flash_mma,  cudaFuncAttributeMaxDynamicSharedMemorySize, FSMEM);

    // Launch order: split+rope(0), gemmQKV(1), flash(2), gemmO(3)
    split_all<<<SPLIT_BLKS + 256, 256>>>(x, Wq, Wk, Wv, Wo,
                                         xhi, xlo, whi, wlo, rtab);

    // Q/K/V projections with fused RoPE/split/transpose epilogues
    {
        dim3 grid(DIM_ / 128, MROWS / 128, 3), block(256);
        gemm_bf16x3<<<grid, block, GSMEM>>>(xhi, xlo, whi, wlo,
                                            nullptr, 1, rtab,
                                            qhi, qlo, khi, klo, vThi, vTlo);
    }
    // flash attention on tensor cores -> chi/clo
    {
        dim3 grid(16, B_ * H_), block(256);
        flash_mma<<<grid, block, FSMEM>>>(qhi, qlo, khi, klo, vThi, vTlo, chi, clo);
    }
    // output projection (plain epilogue)
    {
        dim3 grid(DIM_ / 128, MROWS / 128, 1), block(256);
        gemm_bf16x3<<<grid, block, GSMEM>>>(chi, clo, whi + 3 * (size_t)NK, wlo + 3 * (size_t)NK,
                                            out, 0, rtab,
                                            qhi, qlo, khi, klo, vThi, vTlo);
    }
}

// round 17
// speedup vs baseline: 1.0706x; 1.0210x over previous
#include <cuda_runtime.h>
#include <cuda_bf16.h>
#include <math.h>
#include <cstdint>

#define B_    4
#define S_    2048
#define DIM_  1024
#define H_    16
#define HD_   64
#define BSD   (B_ * S_ * DIM_)     // 8,388,608
#define MROWS (B_ * S_)            // 8192
#define NK    (DIM_ * DIM_)        // 1,048,576

// ---------------- device scratch (no cudaMalloc allowed) -------------------
__device__ __nv_bfloat16 g_xhi[BSD], g_xlo[BSD];
__device__ __nv_bfloat16 g_chi[BSD], g_clo[BSD];
__device__ __nv_bfloat16 g_whi[4 * NK], g_wlo[4 * NK];
__device__ __nv_bfloat16 g_qhi[BSD], g_qlo[BSD];
__device__ __nv_bfloat16 g_khi[BSD], g_klo[BSD];
__device__ __nv_bfloat16 g_vThi[BSD], g_vTlo[BSD];   // layout (b,h,d,s)
__device__ float2 g_rtab[S_ * 32];

// ---------------- PTX helpers (sm_80+ only; NO a-suffix features) ----------
__device__ __forceinline__ uint32_t smem_u32(const void* p) {
    uint32_t a;
    asm("{ .reg .u64 t; cvta.to.shared.u64 t, %1; cvt.u32.u64 %0, t; }"
        : "=r"(a) : "l"(p));
    return a;
}
__device__ __forceinline__ void cp16(uint32_t dst, const void* src) {
    asm volatile("cp.async.cg.shared.global [%0], [%1], 16;"
                 :: "r"(dst), "l"(src));
}
#define CP_COMMIT() asm volatile("cp.async.commit_group;" ::: "memory")
#define CP_WAIT(n)  asm volatile("cp.async.wait_group %0;" :: "n"(n) : "memory")

__device__ __forceinline__ void ldsm_x4(uint32_t* r, uint32_t addr) {
    asm volatile("ldmatrix.sync.aligned.m8n8.x4.shared.b16 {%0,%1,%2,%3}, [%4];"
                 : "=r"(r[0]), "=r"(r[1]), "=r"(r[2]), "=r"(r[3]) : "r"(addr));
}
__device__ __forceinline__ void mma16816(float* c, const uint32_t* a, const uint32_t* b) {
    asm volatile(
        "mma.sync.aligned.m16n8k16.row.col.f32.bf16.bf16.f32 "
        "{%0,%1,%2,%3}, {%4,%5,%6,%7}, {%8,%9}, {%0,%1,%2,%3};"
        : "+f"(c[0]), "+f"(c[1]), "+f"(c[2]), "+f"(c[3])
        : "r"(a[0]), "r"(a[1]), "r"(a[2]), "r"(a[3]), "r"(b[0]), "r"(b[1]));
}

__device__ __forceinline__ void pack_hl(uint32_t& ph, uint32_t& pl, float a, float b) {
    __nv_bfloat162 hb = __floats2bfloat162_rn(a, b);
    float2 hf = __bfloat1622float2(hb);
    __nv_bfloat162 lb = __floats2bfloat162_rn(a - hf.x, b - hf.y);
    ph = reinterpret_cast<uint32_t&>(hb);
    pl = reinterpret_cast<uint32_t&>(lb);
}

// ---------------------------------------------------------------------------
// fused split + rope table. Rope blocks FIRST (blockIdx 0..255) so their
// fp64 sincos latency overlaps the memory-bound split wave (R16 lesson:
// long-pole blocks at the tail serialize; at the head they overlap).
// ---------------------------------------------------------------------------
#define X_N4 (BSD / 4)    // 2,097,152
#define W_N4 (NK / 4)     // 262,144
#define TOT_N4 (X_N4 + 4 * W_N4)
#define SPLIT_BLKS ((TOT_N4 + 255) / 256)   // 12288
#define ROPE_BLKS 256

__global__ __launch_bounds__(256) void split_all(
    const float* __restrict__ x,
    const float* __restrict__ W0, const float* __restrict__ W1,
    const float* __restrict__ W2, const float* __restrict__ W3,
    __nv_bfloat16* __restrict__ xhi, __nv_bfloat16* __restrict__ xlo,
    __nv_bfloat16* __restrict__ whi, __nv_bfloat16* __restrict__ wlo,
    float2* __restrict__ tab)
{
    if (blockIdx.x < ROPE_BLKS) {
        // rope-table part (runs in the first wave, overlapped with splits)
        const int idx = blockIdx.x * 256 + threadIdx.x;   // 0..65535
        const int s = idx >> 5;
        const int i = idx & 31;
        const double inv = exp(-((double)(2 * i) / 64.0) * 9.210340371976184);
        double ang = (double)s * inv;
        const double tp = 6.283185307179586476925287;
        ang -= floor(ang / tp) * tp;
        tab[s * 32 + i] = make_float2((float)cos(ang), (float)sin(ang));
        return;
    }

    const int i = (blockIdx.x - ROPE_BLKS) * blockDim.x + threadIdx.x;
    if (i >= TOT_N4) return;

    const float* src;
    __nv_bfloat16 *hi, *lo;
    int j;
    if (i < X_N4) {
        src = x; hi = xhi; lo = xlo; j = i;
    } else {
        const int wi = i - X_N4;
        const int w = wi >> 18;            // /262144
        j = wi & (W_N4 - 1);
        src = (w == 0) ? W0 : (w == 1) ? W1 : (w == 2) ? W2 : W3;
        hi = whi + (size_t)w * NK;
        lo = wlo + (size_t)w * NK;
    }

    float4 v = ((const float4*)src)[j];
    __nv_bfloat16 h0 = __float2bfloat16(v.x);
    __nv_bfloat16 h1 = __float2bfloat16(v.y);
    __nv_bfloat16 h2 = __float2bfloat16(v.z);
    __nv_bfloat16 h3 = __float2bfloat16(v.w);
    __nv_bfloat16 l0 = __float2bfloat16(v.x - __bfloat162float(h0));
    __nv_bfloat16 l1 = __float2bfloat16(v.y - __bfloat162float(h1));
    __nv_bfloat16 l2 = __float2bfloat16(v.z - __bfloat162float(h2));
    __nv_bfloat16 l3 = __float2bfloat16(v.w - __bfloat162float(h3));
    __nv_bfloat162* hp = (__nv_bfloat162*)(hi + (size_t)j * 4);
    __nv_bfloat162* lp = (__nv_bfloat162*)(lo + (size_t)j * 4);
    hp[0] = __nv_bfloat162(h0, h1); hp[1] = __nv_bfloat162(h2, h3);
    lp[0] = __nv_bfloat162(l0, l1); lp[1] = __nv_bfloat162(l2, l3);
}

// ---------------------------------------------------------------------------
// mma.sync bf16x3-compensated GEMM — FROZEN R14 configuration (measured
// optimum over 7 variants): CTA 128x128, BK=32, 8 warps (2x4), 3-stage
// cp.async with register-rotated bases, ONE barrier/iter, 2 CTAs/SM.
// INVARIANT (R7, R13, R15): prefetch AFTER compute; 2 CTAs/SM mandatory.
// fused=1 (QKV): RoPE/split/transpose epilogues. fused=0 (O): plain fp32.
// q is pre-scaled by 0.125*log2(e) so flash softmax can use exp2 directly.
// ---------------------------------------------------------------------------
#define BK     32
#define NITER  (DIM_ / BK)
#define ATILE  16384                // 128 rows * 128B
#define STAGEB (2 * ATILE)          // A + B = 32768
#define FT_PITCH 130
#define GSMEM  (3 * STAGEB)         // 98304 (FT epilogue needs 66560, fits)
#define QSCALE 0.18033688011112042f // 0.125 * log2(e)

__global__ __launch_bounds__(256, 2) void gemm_bf16x3(
    const __nv_bfloat16* __restrict__ Ahi, const __nv_bfloat16* __restrict__ Alo,
    const __nv_bfloat16* __restrict__ Whi, const __nv_bfloat16* __restrict__ Wlo,
    float* __restrict__ C0,
    int fused,
    const float2* __restrict__ rtab,
    __nv_bfloat16* __restrict__ qhi, __nv_bfloat16* __restrict__ qlo,
    __nv_bfloat16* __restrict__ khi, __nv_bfloat16* __restrict__ klo,
    __nv_bfloat16* __restrict__ vThi, __nv_bfloat16* __restrict__ vTlo)
{
    extern __shared__ char smem[];
    const int tid  = threadIdx.x;
    const int wid  = tid >> 5;
    const int lane = tid & 31;
    const int qq   = lane >> 3;
    const int rr   = lane & 7;
    const int wm   = wid >> 2;
    const int wn   = wid & 3;
    const int z    = blockIdx.z;

    const __nv_bfloat16* Wh = Whi + (size_t)z * NK;
    const __nv_bfloat16* Wl = Wlo + (size_t)z * NK;

    const int m0 = blockIdx.y * 128;
    const int n0 = blockIdx.x * 128;
    const uint32_t sb = smem_u32(smem);

    float acc[4][4][4];
#pragma unroll
    for (int a = 0; a < 4; a++)
#pragma unroll
        for (int b = 0; b < 4; b++)
#pragma unroll
            for (int c = 0; c < 4; c++) acc[a][b][c] = 0.f;

    auto load_stage = [&](uint32_t dbase, int kc) {
#pragma unroll
        for (int t = 0; t < 4; t++) {
            const int idx = tid + t * 256;          // 0..1023
            const int r = idx >> 3, c = idx & 7;    // c: 0-3 hi, 4-7 lo
            const uint32_t doff = r * 128 + ((c ^ (r & 7)) << 4);
            const size_t goff = (size_t)r * DIM_ + kc + (c & 3) * 8;
            const __nv_bfloat16* srcA = (c < 4 ? Ahi : Alo) + (size_t)m0 * DIM_ + goff;
            const __nv_bfloat16* srcB = (c < 4 ? Wh  : Wl ) + (size_t)n0 * DIM_ + goff;
            cp16(dbase + doff,         srcA);
            cp16(dbase + ATILE + doff, srcB);
        }
        CP_COMMIT();
    };

    uint32_t buf0 = sb;
    uint32_t buf1 = sb + STAGEB;
    uint32_t buf2 = sb + 2 * STAGEB;

    load_stage(buf0, 0);
    load_stage(buf1, BK);

    for (int it = 0; it < NITER; it++) {
        if (it + 1 < NITER) CP_WAIT(1);
        else                CP_WAIT(0);
        __syncthreads();

        const uint32_t abase = buf0;
        const uint32_t bbase = buf0 + ATILE;

#pragma unroll
        for (int ks = 0; ks < 2; ks++) {
            uint32_t bh[4][2], bl[4][2];
            const int bch = 2 * ks + (qq & 1);
#pragma unroll
            for (int np = 0; np < 2; np++) {
                const int brow = wn * 32 + np * 16 + (qq >> 1) * 8 + rr;
                const uint32_t sw = brow * 128;
                uint32_t t[4];
                ldsm_x4(t, bbase + sw + ((bch ^ (brow & 7)) << 4));
                bh[2 * np][0] = t[0]; bh[2 * np][1] = t[1];
                bh[2 * np + 1][0] = t[2]; bh[2 * np + 1][1] = t[3];
                ldsm_x4(t, bbase + sw + (((bch + 4) ^ (brow & 7)) << 4));
                bl[2 * np][0] = t[0]; bl[2 * np][1] = t[1];
                bl[2 * np + 1][0] = t[2]; bl[2 * np + 1][1] = t[3];
            }
            const int ach = 2 * ks + (qq >> 1);
#pragma unroll
            for (int mt = 0; mt < 4; mt++) {
                const int arow = wm * 64 + mt * 16 + (qq & 1) * 8 + rr;
                const uint32_t sw = arow * 128;
                uint32_t ah[4], al[4];
                ldsm_x4(ah, abase + sw + ((ach ^ (arow & 7)) << 4));
                ldsm_x4(al, abase + sw + (((ach + 4) ^ (arow & 7)) << 4));
#pragma unroll
                for (int nt = 0; nt < 4; nt++) mma16816(acc[mt][nt], ah, bh[nt]);
#pragma unroll
                for (int nt = 0; nt < 4; nt++) mma16816(acc[mt][nt], ah, bl[nt]);
#pragma unroll
                for (int nt = 0; nt < 4; nt++) mma16816(acc[mt][nt], al, bh[nt]);
            }
        }

        // prefetch stage it+2 AFTER compute (invariant)
        if (it + 2 < NITER)
            load_stage(buf2, (it + 2) * BK);

        const uint32_t tmp = buf0; buf0 = buf1; buf1 = buf2; buf2 = tmp;
    }

    if (!fused) {
#pragma unroll
        for (int mt = 0; mt < 4; mt++)
#pragma unroll
            for (int nt = 0; nt < 4; nt++) {
                const int row = m0 + wm * 64 + mt * 16 + (lane >> 2);
                const int col = n0 + wn * 32 + nt * 8 + (lane & 3) * 2;
                *(float2*)&C0[(size_t)row * DIM_ + col] =
                    make_float2(acc[mt][nt][0], acc[mt][nt][1]);
                *(float2*)&C0[(size_t)(row + 8) * DIM_ + col] =
                    make_float2(acc[mt][nt][2], acc[mt][nt][3]);
            }
        return;
    }

    // ---- fused epilogue: stage fp32 tile in smem (stage buffers are dead) ----
    __syncthreads();
    float* ft = (float*)smem;
#define FT(r, c) ft[(r) * FT_PITCH + (c)]
#pragma unroll
    for (int mt = 0; mt < 4; mt++)
#pragma unroll
        for (int nt = 0; nt < 4; nt++) {
            const int r = wm * 64 + mt * 16 + (lane >> 2);
            const int c = wn * 32 + nt * 8 + (lane & 3) * 2;
            FT(r, c)     = acc[mt][nt][0];
            FT(r, c + 1) = acc[mt][nt][1];
            FT(r + 8, c)     = acc[mt][nt][2];
            FT(r + 8, c + 1) = acc[mt][nt][3];
        }
    __syncthreads();

    if (z < 2) {
        const int r  = tid >> 1;
        const int g  = tid & 1;
        const int m  = m0 + r;
        const int ss = m & (S_ - 1);
        const float scale = (z == 0) ? QSCALE : 1.0f;
        __nv_bfloat16* dh = (z == 0) ? qhi : khi;
        __nv_bfloat16* dl = (z == 0) ? qlo : klo;
        const size_t dst = (size_t)m * DIM_ + n0 + g * 64;
        const float2* trow = rtab + ss * 32;
#pragma unroll
        for (int dc = 0; dc < 32; dc += 8) {
            uint32_t h1[4], l1[4], h2[4], l2[4];
#pragma unroll
            for (int j = 0; j < 4; j++) {
                const int d0 = dc + 2 * j;
                const float2 cs0 = trow[d0];
                const float2 cs1 = trow[d0 + 1];
                const float x1 = FT(r, g * 64 + d0);
                const float x2 = FT(r, g * 64 + d0 + 32);
                const float y1 = FT(r, g * 64 + d0 + 1);
                const float y2 = FT(r, g * 64 + d0 + 33);
                const float o1 = (x1 * cs0.x - x2 * cs0.y) * scale;
                const float o2 = (x2 * cs0.x + x1 * cs0.y) * scale;
                const float p1 = (y1 * cs1.x - y2 * cs1.y) * scale;
                const float p2 = (y2 * cs1.x + y1 * cs1.y) * scale;
                pack_hl(h1[j], l1[j], o1, p1);
                pack_hl(h2[j], l2[j], o2, p2);
            }
            *(uint4*)(dh + dst + dc)      = make_uint4(h1[0], h1[1], h1[2], h1[3]);
            *(uint4*)(dh + dst + dc + 32) = make_uint4(h2[0], h2[1], h2[2], h2[3]);
            *(uint4*)(dl + dst + dc)      = make_uint4(l1[0], l1[1], l1[2], l1[3]);
            *(uint4*)(dl + dst + dc + 32) = make_uint4(l2[0], l2[1], l2[2], l2[3]);
        }
    } else {
        const int col = tid >> 1;           // 0..127
        const int sh  = tid & 1;
        const int gcol = n0 + col;
        const int h   = gcol >> 6, d = gcol & 63;
        const int bb  = m0 >> 11, s0loc = (m0 & (S_ - 1)) + sh * 64;
        const size_t dst = (((size_t)(bb * H_ + h)) * HD_ + d) * S_ + s0loc;
#pragma unroll
        for (int sc = 0; sc < 64; sc += 8) {
            uint32_t hh[4], ll[4];
#pragma unroll
            for (int j = 0; j < 4; j++) {
                const int srow = sh * 64 + sc + 2 * j;
                pack_hl(hh[j], ll[j], FT(srow, col), FT(srow + 1, col));
            }
            *(uint4*)(vThi + dst + sc) = make_uint4(hh[0], hh[1], hh[2], hh[3]);
            *(uint4*)(vTlo + dst + sc) = make_uint4(ll[0], ll[1], ll[2], ll[3]);
        }
    }
#undef FT
}

// ---------------------------------------------------------------------------
// Flash attention on mma.sync bf16x3 (frozen at R14 state).
// ---------------------------------------------------------------------------
#define FROW   144                      // 64 bf16 = 128B + 16B pad
#define QTB    (128 * FROW)             // 18432
#define KTB    (64 * FROW)              // 9216
#define FSTAGE (4 * KTB)                // 36864: khi,klo,vhi,vlo
#define FSMEM  (2 * QTB + 2 * FSTAGE)   // 110592

__global__ __launch_bounds__(256, 2) void flash_mma(
    const __nv_bfloat16* __restrict__ qhi, const __nv_bfloat16* __restrict__ qlo,
    const __nv_bfloat16* __restrict__ khi, const __nv_bfloat16* __restrict__ klo,
    const __nv_bfloat16* __restrict__ vhiT, const __nv_bfloat16* __restrict__ vloT,
    __nv_bfloat16* __restrict__ chi, __nv_bfloat16* __restrict__ clo)
{
    extern __shared__ char smem[];
    const int tid = threadIdx.x, wid = tid >> 5, lane = tid & 31;
    const int qq = lane >> 3, rr = lane & 7;
    const int qt = 15 - blockIdx.x;           // heavy CTAs first
    const int bh = blockIdx.y, b = bh >> 4, h = bh & 15;
    const int q0 = qt * 128;
    const size_t qkbase = (size_t)b * S_ * DIM_ + h * HD_;
    const size_t vbase  = (size_t)bh * 64 * S_;
    const uint32_t sb = smem_u32(smem);
    const uint32_t QHI = 0, QLO = QTB, ST0 = 2 * QTB;

#pragma unroll
    for (int t = 0; t < 8; t++) {
        const int idx = tid + t * 256;
        const int op = idx >> 10;
        const int r = (idx >> 3) & 127, c = idx & 7;
        const __nv_bfloat16* src = (op ? qlo : qhi) + qkbase + (size_t)(q0 + r) * DIM_ + c * 8;
        cp16(sb + (op ? QLO : QHI) + r * FROW + c * 16, src);
    }

    auto load_kv = [&](int kt) {
        const uint32_t d0 = sb + ST0 + (kt & 1) * FSTAGE;
        const int k0 = kt * 64;
#pragma unroll
        for (int t = 0; t < 8; t++) {
            const int idx = tid + t * 256;
            const int which = idx >> 9;
            const int r = (idx >> 3) & 63, c = idx & 7;
            const uint32_t dst = d0 + which * KTB + r * FROW + c * 16;
            const __nv_bfloat16* src;
            if (which == 0)      src = khi  + qkbase + (size_t)(k0 + r) * DIM_ + c * 8;
            else if (which == 1) src = klo  + qkbase + (size_t)(k0 + r) * DIM_ + c * 8;
            else if (which == 2) src = vhiT + vbase + (size_t)r * S_ + k0 + c * 8;
            else                 src = vloT + vbase + (size_t)r * S_ + k0 + c * 8;
            cp16(dst, src);
        }
    };
    load_kv(0); CP_COMMIT();

    float m[2] = {-1e30f, -1e30f}, l[2] = {0.f, 0.f};
    float oacc[8][4];
#pragma unroll
    for (int nt = 0; nt < 8; nt++)
#pragma unroll
        for (int c = 0; c < 4; c++) oacc[nt][c] = 0.f;

    const int rowlo = q0 + wid * 16 + (lane >> 2);
    const int nkt = 2 * (qt + 1);

    for (int kt = 0; kt < nkt; kt++) {
        if (kt + 1 < nkt) { load_kv(kt + 1); CP_COMMIT(); CP_WAIT(1); }
        else              { CP_WAIT(0); }
        __syncthreads();

        const int k0 = kt * 64;
        const bool active = (k0 <= q0 + wid * 16 + 15);
        if (active) {
            const uint32_t kb = sb + ST0 + (kt & 1) * FSTAGE;

            float sacc[8][4];
#pragma unroll
            for (int nt = 0; nt < 8; nt++)
#pragma unroll
                for (int c = 0; c < 4; c++) sacc[nt][c] = 0.f;

#pragma unroll
            for (int kk = 0; kk < 4; kk++) {
                uint32_t aqh[4], aql[4];
                const uint32_t aoff = (wid * 16 + (qq & 1) * 8 + rr) * FROW
                                    + (2 * kk + (qq >> 1)) * 16;
                ldsm_x4(aqh, sb + QHI + aoff);
                ldsm_x4(aql, sb + QLO + aoff);
#pragma unroll
                for (int np = 0; np < 4; np++) {
                    const uint32_t boff = (np * 16 + (qq >> 1) * 8 + rr) * FROW
                                        + (2 * kk + (qq & 1)) * 16;
                    uint32_t th[4], tl[4];
                    ldsm_x4(th, kb + boff);
                    ldsm_x4(tl, kb + KTB + boff);
                    mma16816(sacc[2 * np],     aqh, &th[0]);
                    mma16816(sacc[2 * np + 1], aqh, &th[2]);
                    mma16816(sacc[2 * np],     aqh, &tl[0]);
                    mma16816(sacc[2 * np + 1], aqh, &tl[2]);
                    mma16816(sacc[2 * np],     aql, &th[0]);
                    mma16816(sacc[2 * np + 1], aql, &th[2]);
                }
            }

            if (k0 + 63 > q0 + wid * 16) {
#pragma unroll
                for (int nt = 0; nt < 8; nt++)
#pragma unroll
                    for (int c = 0; c < 4; c++) {
                        const int gcol = k0 + nt * 8 + (lane & 3) * 2 + (c & 1);
                        const int grow = rowlo + ((c >> 1) << 3);
                        if (gcol > grow) sacc[nt][c] = -1e30f;
                    }
            }

            float corr[2];
#pragma unroll
            for (int hh = 0; hh < 2; hh++) {
                float rmax = -1e30f;
#pragma unroll
                for (int nt = 0; nt < 8; nt++)
                    rmax = fmaxf(rmax, fmaxf(sacc[nt][2 * hh], sacc[nt][2 * hh + 1]));
                rmax = fmaxf(rmax, __shfl_xor_sync(0xffffffffu, rmax, 1));
                rmax = fmaxf(rmax, __shfl_xor_sync(0xffffffffu, rmax, 2));
                const float mnew = fmaxf(m[hh], rmax);
                corr[hh] = exp2f(m[hh] - mnew);
                m[hh] = mnew;
                float rsum = 0.f;
#pragma unroll
                for (int nt = 0; nt < 8; nt++) {
                    float p0 = exp2f(sacc[nt][2 * hh]     - mnew);
                    float p1 = exp2f(sacc[nt][2 * hh + 1] - mnew);
                    sacc[nt][2 * hh] = p0; sacc[nt][2 * hh + 1] = p1;
                    rsum += p0 + p1;
                }
                rsum += __shfl_xor_sync(0xffffffffu, rsum, 1);
                rsum += __shfl_xor_sync(0xffffffffu, rsum, 2);
                l[hh] = l[hh] * corr[hh] + rsum;
#pragma unroll
                for (int nt = 0; nt < 8; nt++) {
                    oacc[nt][2 * hh]     *= corr[hh];
                    oacc[nt][2 * hh + 1] *= corr[hh];
                }
            }

#pragma unroll
            for (int kk = 0; kk < 4; kk++) {
                uint32_t ph[4], pl[4];
                pack_hl(ph[0], pl[0], sacc[2 * kk][0],     sacc[2 * kk][1]);
                pack_hl(ph[1], pl[1], sacc[2 * kk][2],     sacc[2 * kk][3]);
                pack_hl(ph[2], pl[2], sacc[2 * kk + 1][0], sacc[2 * kk + 1][1]);
                pack_hl(ph[3], pl[3], sacc[2 * kk + 1][2], sacc[2 * kk + 1][3]);
#pragma unroll
                for (int np = 0; np < 4; np++) {
                    const uint32_t boff = (np * 16 + (qq >> 1) * 8 + rr) * FROW
                                        + (2 * kk + (qq & 1)) * 16;
                    uint32_t th[4], tl[4];
                    ldsm_x4(th, kb + 2 * KTB + boff);
                    ldsm_x4(tl, kb + 3 * KTB + boff);
                    mma16816(oacc[2 * np],     ph, &th[0]);
                    mma16816(oacc[2 * np + 1], ph, &th[2]);
                    mma16816(oacc[2 * np],     ph, &tl[0]);
                    mma16816(oacc[2 * np + 1], ph, &tl[2]);
                    mma16816(oacc[2 * np],     pl, &th[0]);
                    mma16816(oacc[2 * np + 1], pl, &th[2]);
                }
            }
        }
        __syncthreads();
    }

    const float inv0 = 1.f / l[0], inv1 = 1.f / l[1];
#pragma unroll
    for (int nt = 0; nt < 8; nt++) {
#pragma unroll
        for (int hh = 0; hh < 2; hh++) {
            const float inv = hh ? inv1 : inv0;
            const int row = rowlo + 8 * hh;
            const size_t off = ((size_t)b * S_ + row) * DIM_ + h * HD_
                             + nt * 8 + (lane & 3) * 2;
            uint32_t ph, pl;
            pack_hl(ph, pl, oacc[nt][2 * hh] * inv, oacc[nt][2 * hh + 1] * inv);
            *(uint32_t*)(chi + off) = ph;
            *(uint32_t*)(clo + off) = pl;
        }
    }
}

// ---------------------------------------------------------------------------
extern "C" void kernel_launch(void* const* d_in, const int* in_sizes, int n_in,
                              void* d_out, int out_size)
{
    (void)in_sizes; (void)n_in; (void)out_size;
    const float* x  = (const float*)d_in[0];
    const float* Wq = (const float*)d_in[1];
    const float* Wk = (const float*)d_in[2];
    const float* Wv = (const float*)d_in[3];
    const float* Wo = (const float*)d_in[4];
    float* out = (float*)d_out;

    __nv_bfloat16 *xhi, *xlo, *chi, *clo, *whi, *wlo;
    __nv_bfloat16 *qhi, *qlo, *khi, *klo, *vThi, *vTlo;
    float2* rtab;
    cudaGetSymbolAddress((void**)&xhi,  g_xhi);
    cudaGetSymbolAddress((void**)&xlo,  g_xlo);
    cudaGetSymbolAddress((void**)&chi,  g_chi);
    cudaGetSymbolAddress((void**)&clo,  g_clo);
    cudaGetSymbolAddress((void**)&whi,  g_whi);
    cudaGetSymbolAddress((void**)&wlo,  g_wlo);
    cudaGetSymbolAddress((void**)&qhi,  g_qhi);
    cudaGetSymbolAddress((void**)&qlo,  g_qlo);
    cudaGetSymbolAddress((void**)&khi,  g_khi);
    cudaGetSymbolAddress((void**)&klo,  g_klo);
    cudaGetSymbolAddress((void**)&vThi, g_vThi);
    cudaGetSymbolAddress((void**)&vTlo, g_vTlo);
    cudaGetSymbolAddress((void**)&rtab, g_rtab);

    cudaFuncSetAttribute(gemm_bf16x3, cudaFuncAttributeMaxDynamicSharedMemorySize, GSMEM);
    cudaFuncSetAttribute(flash_mma,  cudaFuncAttributeMaxDynamicSharedMemorySize, FSMEM);

    // Launch order: split+rope(0) [rope blocks first], gemmQKV(1), flash(2), gemmO(3)
    split_all<<<ROPE_BLKS + SPLIT_BLKS, 256>>>(x, Wq, Wk, Wv, Wo,
                                               xhi, xlo, whi, wlo, rtab);

    // Q/K/V projections with fused RoPE/split/transpose epilogues
    {
        dim3 grid(DIM_ / 128, MROWS / 128, 3), block(256);
        gemm_bf16x3<<<grid, block, GSMEM>>>(xhi, xlo, whi, wlo,
                                            nullptr, 1, rtab,
                                            qhi, qlo, khi, klo, vThi, vTlo);
    }
    // flash attention on tensor cores -> chi/clo
    {
        dim3 grid(16, B_ * H_), block(256);
        flash_mma<<<grid, block, FSMEM>>>(qhi, qlo, khi, klo, vThi, vTlo, chi, clo);
    }
    // output projection (plain epilogue)
    {
        dim3 grid(DIM_ / 128, MROWS / 128, 1), block(256);
        gemm_bf16x3<<<grid, block, GSMEM>>>(chi, clo, whi + 3 * (size_t)NK, wlo + 3 * (size_t)NK,
                                            out, 0, rtab,
                                            qhi, qlo, khi, klo, vThi, vTlo);
    }
}